// round 5
// baseline (speedup 1.0000x reference)
#include <cuda_runtime.h>
#include <cuda_bf16.h>
#include <cstdint>

#define DIMX      2048
#define D_STATE_  128
#define NHEADS_   64
#define HEADDIM_  64
#define D_INNER_  4096
#define D_IN_PROJ_ 8512
#define CONV_DIM_ 4352
#define BATCH_    2
#define SEQ_      2048
#define MROWS_    4096
#define DT_OFF_   8448
#define NPAD_IN_  8704

typedef __nv_bfloat16 bf16;
typedef unsigned long long u64;

// ---------------- device scratch ----------------
__device__ __align__(16)  float g_wpartA[1024];
__device__ __align__(16)  float g_wpartB[1024];
__device__                float g_wscale[2];
__device__ __align__(128) bf16  g_WqIn[(size_t)NPAD_IN_ * DIMX];
__device__ __align__(128) bf16  g_WqOut[(size_t)DIMX * D_INNER_];
__device__ __align__(128) bf16  g_Aq[(size_t)MROWS_ * DIMX];
__device__ __align__(128) bf16  g_Yq[(size_t)MROWS_ * D_INNER_];
__device__                float g_sA[MROWS_];
__device__                float g_sY[MROWS_];
__device__ __align__(128) float g_ZX[(size_t)MROWS_ * D_IN_PROJ_];
__device__ __align__(128) float g_XC[(size_t)MROWS_ * CONV_DIM_];
__device__ __align__(128) float g_Y[(size_t)MROWS_ * D_INNER_];

// ---------------- helpers ----------------
__device__ __forceinline__ uint32_t smem_u32(const void* p) {
    uint32_t a;
    asm("{ .reg .u64 t; cvta.to.shared.u64 t, %1; cvt.u32.u64 %0, t; }" : "=r"(a) : "l"(p));
    return a;
}
__device__ __forceinline__ u64 pk2(float lo, float hi) { u64 r; asm("mov.b64 %0, {%1,%2};" : "=l"(r) : "f"(lo), "f"(hi)); return r; }
__device__ __forceinline__ void upk2(float& lo, float& hi, u64 v) { asm("mov.b64 {%0,%1}, %2;" : "=f"(lo), "=f"(hi) : "l"(v)); }
__device__ __forceinline__ u64 fma2(u64 a, u64 b, u64 c) { u64 d; asm("fma.rn.f32x2 %0, %1, %2, %3;" : "=l"(d) : "l"(a), "l"(b), "l"(c)); return d; }
__device__ __forceinline__ u64 mul2(u64 a, u64 b) { u64 d; asm("mul.rn.f32x2 %0, %1, %2;" : "=l"(d) : "l"(a), "l"(b)); return d; }

// ---------------- block reduce ----------------
template<bool MAXOP>
__device__ __forceinline__ float blockReduce(float v) {
    __shared__ float sm[8];
    int lane = threadIdx.x & 31, wid = threadIdx.x >> 5;
    #pragma unroll
    for (int o = 16; o; o >>= 1) {
        float u = __shfl_xor_sync(0xffffffffu, v, o);
        v = MAXOP ? fmaxf(v, u) : v + u;
    }
    if (lane == 0) sm[wid] = v;
    __syncthreads();
    if (threadIdx.x < 32) {
        v = (lane < 8) ? sm[lane] : (MAXOP ? -3.4e38f : 0.f);
        #pragma unroll
        for (int o = 4; o; o >>= 1) {
            float u = __shfl_xor_sync(0xffffffffu, v, o);
            v = MAXOP ? fmaxf(v, u) : v + u;
        }
        if (lane == 0) sm[0] = v;
    }
    __syncthreads();
    v = sm[0];
    __syncthreads();
    return v;
}

// ---------------- merged |w| partial sums (both matrices, one launch) ------
__global__ void k_absboth(const float4* __restrict__ w1, const float4* __restrict__ w2,
                          long n41, long n42) {
    int which = blockIdx.x >= 1024;
    int blk = which ? blockIdx.x - 1024 : blockIdx.x;
    const float4* w = which ? w2 : w1;
    long n4 = which ? n42 : n41;
    float s = 0.f;
    for (long i = (long)blk * 256 + threadIdx.x; i < n4; i += 1024L * 256) {
        float4 v = w[i];
        s += fabsf(v.x) + fabsf(v.y) + fabsf(v.z) + fabsf(v.w);
    }
    s = blockReduce<false>(s);
    if (threadIdx.x == 0) (which ? g_wpartB : g_wpartA)[blk] = s;
}
__global__ void k_wscale_final() {
    float a = 0.f, b = 0.f;
    for (int i = threadIdx.x; i < 1024; i += 256) { a += g_wpartA[i]; b += g_wpartB[i]; }
    a = blockReduce<false>(a);
    b = blockReduce<false>(b);
    if (threadIdx.x == 0) {
        g_wscale[0] = fmaxf(a / ((float)D_IN_PROJ_ * (float)DIMX), 1e-5f);
        g_wscale[1] = fmaxf(b / ((float)DIMX * (float)D_INNER_), 1e-5f);
    }
}
// merged ternary quantize for both weights + zero-pad of g_WqIn tail
#define NQ1 ((long)D_IN_PROJ_ * DIMX / 4)
#define NQ2 ((long)DIMX * D_INNER_ / 4)
#define NQP ((long)(NPAD_IN_ - D_IN_PROJ_) * DIMX / 4)
__global__ void k_wquant_all(const float* __restrict__ w1, const float* __restrict__ w2) {
    long q = (long)blockIdx.x * 256 + threadIdx.x;
    const float* w; bf16* dst; float sc; long i;
    if (q < NQ1) { w = w1; dst = g_WqIn;  sc = g_wscale[0]; i = q * 4; }
    else if (q < NQ1 + NQ2) { w = w2; dst = g_WqOut; sc = g_wscale[1]; i = (q - NQ1) * 4; }
    else if (q < NQ1 + NQ2 + NQP) {
        long i2 = (q - NQ1 - NQ2) * 4;
        *(uint2*)(g_WqIn + (size_t)D_IN_PROJ_ * DIMX + i2) = make_uint2(0, 0);
        return;
    } else return;
    float4 v = *(const float4*)(w + i);
    float vv[4] = {v.x, v.y, v.z, v.w};
    bf16 o[4];
    #pragma unroll
    for (int j = 0; j < 4; j++) {
        float ws = vv[j] / sc;
        float qq = (ws >= 0.f) ? floorf(ws + 0.5f) : ceilf(ws - 0.5f);
        o[j] = __float2bfloat16(fminf(fmaxf(qq, -1.f), 1.f));
    }
    *(uint2*)(dst + i) = *(uint2*)o;
}

// ---------------- fused norms + activation quant ----------------
template<int W, int WHICH>
__global__ void k_actquant(const float* __restrict__ X, const float* __restrict__ nw) {
    constexpr int VPT = W / 256;
    const int row = blockIdx.x, tid = threadIdx.x;
    const float* xr = (WHICH ? g_Y : X) + (size_t)row * W;
    float x[VPT];
    float ss = 0.f;
    #pragma unroll
    for (int i = 0; i < VPT; i++) { x[i] = xr[tid + i * 256]; ss += x[i] * x[i]; }
    ss = blockReduce<false>(ss);
    float r = rsqrtf(ss / (float)W + 1e-6f);
    float h[VPT]; float sum = 0.f, sq = 0.f;
    #pragma unroll
    for (int i = 0; i < VPT; i++) {
        h[i] = nw[tid + i * 256] * x[i] * r;
        sum += h[i]; sq += h[i] * h[i];
    }
    sum = blockReduce<false>(sum);
    sq  = blockReduce<false>(sq);
    float mean = sum / (float)W;
    float var  = sq / (float)W - mean * mean;
    float rv = rsqrtf(var + 1e-5f);
    float amax = 0.f;
    #pragma unroll
    for (int i = 0; i < VPT; i++) {
        h[i] = (h[i] - mean) * rv;
        amax = fmaxf(amax, fabsf(h[i]));
    }
    amax = blockReduce<true>(amax);
    float scale = 127.f / fmaxf(amax, 1e-5f);
    bf16* Q = WHICH ? g_Yq : g_Aq;
    #pragma unroll
    for (int i = 0; i < VPT; i++) {
        float q = rintf(h[i] * scale);
        q = fminf(fmaxf(q, -128.f), 127.f);
        Q[(size_t)row * W + tid + i * 256] = __float2bfloat16(q);
    }
    if (tid == 0) (WHICH ? g_sY : g_sA)[row] = scale;
}

// ---------------- pipelined mma.sync GEMM: 128x256 tile, 512 threads -------
#define BMg 128
#define BNg 256
#define BKg 32
#define LDSg 40
#define A_ELEMS (BMg * LDSg)                 // 5120
#define B_ELEMS (BNg * LDSg)                 // 10240
#define STG_BYTES ((A_ELEMS + B_ELEMS) * 2)  // 30720
#define GEMM_SMEM (4 * STG_BYTES)            // 122880

template<int MODE>
__global__ void __launch_bounds__(512, 1) k_gemm(const float* __restrict__ resid,
                                                 float* __restrict__ outp) {
    constexpr int K = MODE ? D_INNER_ : DIMX;
    constexpr int N = MODE ? DIMX : D_IN_PROJ_;
    constexpr int NS = K / BKg;

    const bf16*  __restrict__ A  = MODE ? g_Yq : g_Aq;
    const bf16*  __restrict__ Bw = MODE ? g_WqOut : g_WqIn;
    const float* __restrict__ rs = MODE ? g_sY : g_sA;
    float*       __restrict__ C  = MODE ? outp : g_ZX;

    extern __shared__ char smem[];
    const uint32_t sb = smem_u32(smem);

    const int tid = threadIdx.x;
    const int lane = tid & 31, wid = tid >> 5;
    const int wm = wid & 1, wn = wid >> 1;        // 2 x 8 warp grid
    const int m0 = blockIdx.y * BMg, n0 = blockIdx.x * BNg;
    const int mw = wm * 64, nwp = wn * 32;

    float acc[4][4][4];
    #pragma unroll
    for (int a = 0; a < 4; a++)
        #pragma unroll
        for (int b = 0; b < 4; b++)
            #pragma unroll
            for (int c = 0; c < 4; c++) acc[a][b][c] = 0.f;

    // copy plan: per stage A 512 + B 1024 = 1536 chunks of 16B; 3 per thread
    const bf16* gsrc[3];
    uint32_t sdst[3];
    #pragma unroll
    for (int i = 0; i < 3; i++) {
        int q = tid + i * 512;
        if (q < 512) {
            int row = q >> 2, c = q & 3;
            gsrc[i] = A + (size_t)(m0 + row) * K + c * 8;
            sdst[i] = (uint32_t)(row * LDSg + c * 8) * 2;
        } else {
            int qq = q - 512, row = qq >> 2, c = qq & 3;
            gsrc[i] = Bw + (size_t)(n0 + row) * K + c * 8;
            sdst[i] = (uint32_t)(A_ELEMS + row * LDSg + c * 8) * 2;
        }
    }

    #define LOAD_STAGE(s_) do { \
        uint32_t base_ = sb + ((s_) & 3) * STG_BYTES; \
        _Pragma("unroll") \
        for (int i_ = 0; i_ < 3; i_++) \
            asm volatile("cp.async.cg.shared.global [%0], [%1], 16;" \
                :: "r"(base_ + sdst[i_]), "l"(gsrc[i_] + (s_) * BKg) : "memory"); \
        asm volatile("cp.async.commit_group;" ::: "memory"); \
    } while (0)

    uint32_t aOff[4], bOff[2];
    {
        int rA = mw + (lane & 15);
        int cA = (lane >> 4) * 8;
        #pragma unroll
        for (int fm = 0; fm < 4; fm++)
            aOff[fm] = (uint32_t)((rA + fm * 16) * LDSg + cA) * 2;
        int rB = nwp + ((lane >> 4) << 3) + (lane & 7);
        int cB = ((lane >> 3) & 1) * 8;
        #pragma unroll
        for (int fb = 0; fb < 2; fb++)
            bOff[fb] = (uint32_t)(A_ELEMS + (rB + fb * 16) * LDSg + cB) * 2;
    }

    LOAD_STAGE(0); LOAD_STAGE(1); LOAD_STAGE(2);

    for (int s = 0; s < NS; s++) {
        asm volatile("cp.async.wait_group 2;" ::: "memory");
        __syncthreads();
        if (s + 3 < NS) LOAD_STAGE(s + 3);

        const uint32_t base = sb + (s & 3) * STG_BYTES;
        #pragma unroll
        for (int ks = 0; ks < BKg; ks += 16) {
            unsigned af[4][4], bfr[4][2];
            #pragma unroll
            for (int fm = 0; fm < 4; fm++)
                asm volatile("ldmatrix.sync.aligned.m8n8.x4.shared.b16 {%0,%1,%2,%3}, [%4];"
                    : "=r"(af[fm][0]), "=r"(af[fm][1]), "=r"(af[fm][2]), "=r"(af[fm][3])
                    : "r"(base + aOff[fm] + (uint32_t)(ks * 2)));
            #pragma unroll
            for (int fb = 0; fb < 2; fb++) {
                unsigned q0, q1, q2, q3;
                asm volatile("ldmatrix.sync.aligned.m8n8.x4.shared.b16 {%0,%1,%2,%3}, [%4];"
                    : "=r"(q0), "=r"(q1), "=r"(q2), "=r"(q3)
                    : "r"(base + bOff[fb] + (uint32_t)(ks * 2)));
                bfr[fb * 2][0] = q0; bfr[fb * 2][1] = q1;
                bfr[fb * 2 + 1][0] = q2; bfr[fb * 2 + 1][1] = q3;
            }
            #pragma unroll
            for (int fm = 0; fm < 4; fm++)
                #pragma unroll
                for (int fn = 0; fn < 4; fn++)
                    asm volatile("mma.sync.aligned.m16n8k16.row.col.f32.bf16.bf16.f32 "
                        "{%0,%1,%2,%3},{%4,%5,%6,%7},{%8,%9},{%0,%1,%2,%3};"
                        : "+f"(acc[fm][fn][0]), "+f"(acc[fm][fn][1]),
                          "+f"(acc[fm][fn][2]), "+f"(acc[fm][fn][3])
                        : "r"(af[fm][0]), "r"(af[fm][1]), "r"(af[fm][2]), "r"(af[fm][3]),
                          "r"(bfr[fn][0]), "r"(bfr[fn][1]));
        }
    }

    const int mr = m0 + mw + (lane >> 2);
    const int nc = n0 + nwp + (lane & 3) * 2;
    #pragma unroll
    for (int fm = 0; fm < 4; fm++) {
        int m = mr + fm * 16;
        float inv0 = 1.f / rs[m];
        float inv1 = 1.f / rs[m + 8];
        #pragma unroll
        for (int fn = 0; fn < 4; fn++) {
            int n = nc + fn * 8;
            if (n < N) {
                size_t o0 = (size_t)m * N + n;
                size_t o8 = (size_t)(m + 8) * N + n;
                float v0 = acc[fm][fn][0] * inv0;
                float v1 = acc[fm][fn][1] * inv0;
                float v2 = acc[fm][fn][2] * inv1;
                float v3 = acc[fm][fn][3] * inv1;
                if (MODE) {
                    v0 += resid[o0]; v1 += resid[o0 + 1];
                    v2 += resid[o8]; v3 += resid[o8 + 1];
                }
                C[o0] = v0; C[o0 + 1] = v1; C[o8] = v2; C[o8 + 1] = v3;
            }
        }
    }
    #undef LOAD_STAGE
}

// ---------------- causal conv1d + silu: sliding window ----------------
__global__ void k_conv(const float* __restrict__ cw, const float* __restrict__ cb) {
    int c = blockIdx.x * 256 + threadIdx.x;
    if (c >= CONV_DIM_) return;
    int b = blockIdx.y >> 3;
    int s0 = (blockIdx.y & 7) * 256;
    const float* src = g_ZX + (size_t)(b * SEQ_) * D_IN_PROJ_ + D_INNER_ + c;
    float*       dst = g_XC + (size_t)(b * SEQ_) * CONV_DIM_ + c;
    const float w0 = cw[c * 4], w1 = cw[c * 4 + 1], w2 = cw[c * 4 + 2], w3 = cw[c * 4 + 3];
    const float bias = cb[c];
    float xm3 = 0.f, xm2 = 0.f, xm1 = 0.f;
    if (s0 > 0) {
        xm3 = src[(size_t)(s0 - 3) * D_IN_PROJ_];
        xm2 = src[(size_t)(s0 - 2) * D_IN_PROJ_];
        xm1 = src[(size_t)(s0 - 1) * D_IN_PROJ_];
    }
    #pragma unroll 4
    for (int l = s0; l < s0 + 256; l++) {
        float x0 = src[(size_t)l * D_IN_PROJ_];
        float acc = fmaf(w3, x0, fmaf(w2, xm1, fmaf(w1, xm2, fmaf(w0, xm3, bias))));
        dst[(size_t)l * CONV_DIM_] = acc / (1.f + expf(-acc));
        xm3 = xm2; xm2 = xm1; xm1 = x0;
    }
}

// ---------------- recurrent SSD scan: 2 steps per barrier ----------------
__global__ void __launch_bounds__(512) k_scan(const float* __restrict__ A_log,
                                              const float* __restrict__ Dv,
                                              const float* __restrict__ dt_bias) {
    const int bh = blockIdx.x;
    const int h = bh & (NHEADS_ - 1);
    const int b = bh >> 6;
    const int t = threadIdx.x;
    const int pc = t & 63, gc = t >> 6, n0 = gc * 16;

    __shared__ __align__(16) float xs[2][2][64], zs[2][2][64];
    __shared__ __align__(16) float Bsh[2][2][128], Csh[2][2][128];
    __shared__ __align__(16) float ypart[2][2][8][64];
    __shared__ float sdt[2][2], sdA[2][2];

    const float Ah   = -expf(A_log[h]);
    const float Dh   = Dv[h];
    const float bias = dt_bias[h];

    u64 h2[8];
    #pragma unroll
    for (int i = 0; i < 8; i++) h2[i] = 0ull;

    const float* gptr = nullptr;
    if      (t < 64)  gptr = g_XC + (size_t)(b * SEQ_) * CONV_DIM_ + h * 64 + t;
    else if (t < 192) gptr = g_XC + (size_t)(b * SEQ_) * CONV_DIM_ + D_INNER_ + (t - 64);
    else if (t < 320) gptr = g_XC + (size_t)(b * SEQ_) * CONV_DIM_ + D_INNER_ + D_STATE_ + (t - 192);
    else if (t < 384) gptr = g_ZX + (size_t)(b * SEQ_) * D_IN_PROJ_ + h * 64 + (t - 320);
    else if (t == 384) gptr = g_ZX + (size_t)(b * SEQ_) * D_IN_PROJ_ + DT_OFF_ + h;
    const size_t stride = (t < 320) ? (size_t)CONV_DIM_ : (size_t)D_IN_PROJ_;

    float v0 = 0.f, v1 = 0.f;
    if (gptr) { v0 = gptr[0]; v1 = gptr[stride]; }
    float* yrow = g_Y + (size_t)(b * SEQ_) * D_INNER_ + h * 64;

    for (int blk = 0; blk < SEQ_ / 2; blk++) {
        const int p = blk & 1, q = p ^ 1;
        if      (t < 64)  { xs[p][0][t] = v0;        xs[p][1][t] = v1; }
        else if (t < 192) { Bsh[p][0][t - 64] = v0;  Bsh[p][1][t - 64] = v1; }
        else if (t < 320) { Csh[p][0][t - 192] = v0; Csh[p][1][t - 192] = v1; }
        else if (t < 384) { zs[p][0][t - 320] = v0;  zs[p][1][t - 320] = v1; }
        else if (t == 384) {
            float d0 = v0 + bias;
            float sp0 = fmaxf(d0, 0.f) + log1pf(expf(-fabsf(d0)));
            sdt[p][0] = sp0; sdA[p][0] = expf(sp0 * Ah);
            float d1 = v1 + bias;
            float sp1 = fmaxf(d1, 0.f) + log1pf(expf(-fabsf(d1)));
            sdt[p][1] = sp1; sdA[p][1] = expf(sp1 * Ah);
        }
        __syncthreads();

        if (blk > 0 && t < 64) {
            #pragma unroll
            for (int s = 0; s < 2; s++) {
                float ysum = 0.f;
                #pragma unroll
                for (int g = 0; g < 8; g++) ysum += ypart[q][s][g][t];
                float xv = xs[q][s][t], zz = zs[q][s][t];
                float yo = (ysum + Dh * xv) * (zz / (1.f + expf(-zz)));
                yrow[(size_t)(2 * (blk - 1) + s) * D_INNER_ + t] = yo;
            }
        }

        float v0n = 0.f, v1n = 0.f;
        if (gptr && blk + 1 < SEQ_ / 2) {
            v0n = gptr[(size_t)(2 * blk + 2) * stride];
            v1n = gptr[(size_t)(2 * blk + 3) * stride];
        }

        #pragma unroll
        for (int s = 0; s < 2; s++) {
            const float dA = sdA[p][s];
            const float cf = sdt[p][s] * xs[p][s][pc];
            const u64 dA2 = pk2(dA, dA);
            const u64 cf2 = pk2(cf, cf);
            u64 y2 = 0ull;
            #pragma unroll
            for (int i = 0; i < 8; i++) {
                u64 B2 = *(const u64*)&Bsh[p][s][n0 + 2 * i];
                u64 C2 = *(const u64*)&Csh[p][s][n0 + 2 * i];
                h2[i] = fma2(h2[i], dA2, mul2(cf2, B2));
                y2 = fma2(h2[i], C2, y2);
            }
            float ylo, yhi; upk2(ylo, yhi, y2);
            ypart[p][s][gc][pc] = ylo + yhi;
        }

        v0 = v0n; v1 = v1n;
    }
    __syncthreads();
    if (t < 64) {
        const int q = (SEQ_ / 2 - 1) & 1;
        #pragma unroll
        for (int s = 0; s < 2; s++) {
            float ysum = 0.f;
            #pragma unroll
            for (int g = 0; g < 8; g++) ysum += ypart[q][s][g][t];
            float xv = xs[q][s][t], zz = zs[q][s][t];
            float yo = (ysum + Dh * xv) * (zz / (1.f + expf(-zz)));
            yrow[(size_t)(SEQ_ - 2 + s) * D_INNER_ + t] = yo;
        }
    }
}

// ---------------- launch ----------------
extern "C" void kernel_launch(void* const* d_in, const int* in_sizes, int n_in,
                              void* d_out, int out_size) {
    const float* hidden     = (const float*)d_in[0];
    const float* in_proj    = (const float*)d_in[1];
    const float* out_proj   = (const float*)d_in[2];
    const float* conv_w     = (const float*)d_in[3];
    const float* conv_b     = (const float*)d_in[4];
    const float* A_log      = (const float*)d_in[5];
    const float* Dv         = (const float*)d_in[6];
    const float* dt_bias    = (const float*)d_in[7];
    const float* norm_w     = (const float*)d_in[8];
    const float* out_norm_w = (const float*)d_in[9];
    float* out = (float*)d_out;

    const long nW1 = (long)D_IN_PROJ_ * DIMX;
    const long nW2 = (long)DIMX * D_INNER_;
    const long nQAll = NQ1 + NQ2 + NQP;

    cudaFuncSetAttribute(k_gemm<0>, cudaFuncAttributeMaxDynamicSharedMemorySize, GEMM_SMEM);
    cudaFuncSetAttribute(k_gemm<1>, cudaFuncAttributeMaxDynamicSharedMemorySize, GEMM_SMEM);

    k_absboth<<<2048, 256>>>((const float4*)in_proj, (const float4*)out_proj, nW1 / 4, nW2 / 4);
    k_wscale_final<<<1, 256>>>();
    k_wquant_all<<<(unsigned)((nQAll + 255) / 256), 256>>>(in_proj, out_proj);
    k_actquant<DIMX, 0><<<MROWS_, 256>>>(hidden, norm_w);
    k_gemm<0><<<dim3(NPAD_IN_ / 256, MROWS_ / 128), 512, GEMM_SMEM>>>(nullptr, nullptr);
    k_conv<<<dim3((CONV_DIM_ + 255) / 256, BATCH_ * 8), 256>>>(conv_w, conv_b);
    k_scan<<<BATCH_ * NHEADS_, 512>>>(A_log, Dv, dt_bias);
    k_actquant<D_INNER_, 1><<<MROWS_, 256>>>(nullptr, out_norm_w);
    k_gemm<1><<<dim3(DIMX / 256, MROWS_ / 128), 512, GEMM_SMEM>>>(hidden, out);
}

// round 6
// speedup vs baseline: 1.0572x; 1.0572x over previous
#include <cuda_runtime.h>
#include <cuda_bf16.h>
#include <cstdint>

#define DIMX      2048
#define D_STATE_  128
#define NHEADS_   64
#define HEADDIM_  64
#define D_INNER_  4096
#define D_IN_PROJ_ 8512
#define CONV_DIM_ 4352
#define BATCH_    2
#define SEQ_      2048
#define MROWS_    4096
#define DT_OFF_   8448
#define NPAD_IN_  8704

typedef __nv_bfloat16 bf16;
typedef unsigned long long u64;

// ---------------- device scratch ----------------
__device__ __align__(16)  float g_wpartA[1024];
__device__ __align__(16)  float g_wpartB[1024];
__device__                float g_wscale[2];
__device__ __align__(128) bf16  g_WqIn[(size_t)NPAD_IN_ * DIMX];
__device__ __align__(128) bf16  g_WqOut[(size_t)DIMX * D_INNER_];
__device__ __align__(128) bf16  g_Aq[(size_t)MROWS_ * DIMX];
__device__ __align__(128) bf16  g_Yq[(size_t)MROWS_ * D_INNER_];
__device__                float g_sA[MROWS_];
__device__                float g_sY[MROWS_];
__device__ __align__(128) float g_ZX[(size_t)MROWS_ * D_IN_PROJ_];
__device__ __align__(128) float g_XC[(size_t)MROWS_ * CONV_DIM_];
__device__ __align__(128) float g_Y[(size_t)MROWS_ * D_INNER_];

// ---------------- helpers ----------------
__device__ __forceinline__ uint32_t smem_u32(const void* p) {
    uint32_t a;
    asm("{ .reg .u64 t; cvta.to.shared.u64 t, %1; cvt.u32.u64 %0, t; }" : "=r"(a) : "l"(p));
    return a;
}
__device__ __forceinline__ u64 pk2(float lo, float hi) { u64 r; asm("mov.b64 %0, {%1,%2};" : "=l"(r) : "f"(lo), "f"(hi)); return r; }
__device__ __forceinline__ void upk2(float& lo, float& hi, u64 v) { asm("mov.b64 {%0,%1}, %2;" : "=f"(lo), "=f"(hi) : "l"(v)); }
__device__ __forceinline__ u64 fma2(u64 a, u64 b, u64 c) { u64 d; asm("fma.rn.f32x2 %0, %1, %2, %3;" : "=l"(d) : "l"(a), "l"(b), "l"(c)); return d; }
__device__ __forceinline__ u64 mul2(u64 a, u64 b) { u64 d; asm("mul.rn.f32x2 %0, %1, %2;" : "=l"(d) : "l"(a), "l"(b)); return d; }

// ---------------- block reduce ----------------
template<bool MAXOP>
__device__ __forceinline__ float blockReduce(float v) {
    __shared__ float sm[8];
    int lane = threadIdx.x & 31, wid = threadIdx.x >> 5;
    #pragma unroll
    for (int o = 16; o; o >>= 1) {
        float u = __shfl_xor_sync(0xffffffffu, v, o);
        v = MAXOP ? fmaxf(v, u) : v + u;
    }
    if (lane == 0) sm[wid] = v;
    __syncthreads();
    if (threadIdx.x < 32) {
        v = (lane < 8) ? sm[lane] : (MAXOP ? -3.4e38f : 0.f);
        #pragma unroll
        for (int o = 4; o; o >>= 1) {
            float u = __shfl_xor_sync(0xffffffffu, v, o);
            v = MAXOP ? fmaxf(v, u) : v + u;
        }
        if (lane == 0) sm[0] = v;
    }
    __syncthreads();
    v = sm[0];
    __syncthreads();
    return v;
}

// ---------------- merged |w| partial sums ----------------
__global__ void k_absboth(const float4* __restrict__ w1, const float4* __restrict__ w2,
                          long n41, long n42) {
    int which = blockIdx.x >= 1024;
    int blk = which ? blockIdx.x - 1024 : blockIdx.x;
    const float4* w = which ? w2 : w1;
    long n4 = which ? n42 : n41;
    float s = 0.f;
    for (long i = (long)blk * 256 + threadIdx.x; i < n4; i += 1024L * 256) {
        float4 v = w[i];
        s += fabsf(v.x) + fabsf(v.y) + fabsf(v.z) + fabsf(v.w);
    }
    s = blockReduce<false>(s);
    if (threadIdx.x == 0) (which ? g_wpartB : g_wpartA)[blk] = s;
}
__global__ void k_wscale_final() {
    float a = 0.f, b = 0.f;
    for (int i = threadIdx.x; i < 1024; i += 256) { a += g_wpartA[i]; b += g_wpartB[i]; }
    a = blockReduce<false>(a);
    b = blockReduce<false>(b);
    if (threadIdx.x == 0) {
        g_wscale[0] = fmaxf(a / ((float)D_IN_PROJ_ * (float)DIMX), 1e-5f);
        g_wscale[1] = fmaxf(b / ((float)DIMX * (float)D_INNER_), 1e-5f);
    }
}
#define NQ1 ((long)D_IN_PROJ_ * DIMX / 4)
#define NQ2 ((long)DIMX * D_INNER_ / 4)
#define NQP ((long)(NPAD_IN_ - D_IN_PROJ_) * DIMX / 4)
__global__ void k_wquant_all(const float* __restrict__ w1, const float* __restrict__ w2) {
    long q = (long)blockIdx.x * 256 + threadIdx.x;
    const float* w; bf16* dst; float sc; long i;
    if (q < NQ1) { w = w1; dst = g_WqIn;  sc = g_wscale[0]; i = q * 4; }
    else if (q < NQ1 + NQ2) { w = w2; dst = g_WqOut; sc = g_wscale[1]; i = (q - NQ1) * 4; }
    else if (q < NQ1 + NQ2 + NQP) {
        long i2 = (q - NQ1 - NQ2) * 4;
        *(uint2*)(g_WqIn + (size_t)D_IN_PROJ_ * DIMX + i2) = make_uint2(0, 0);
        return;
    } else return;
    float4 v = *(const float4*)(w + i);
    float vv[4] = {v.x, v.y, v.z, v.w};
    bf16 o[4];
    #pragma unroll
    for (int j = 0; j < 4; j++) {
        float ws = vv[j] / sc;
        float qq = (ws >= 0.f) ? floorf(ws + 0.5f) : ceilf(ws - 0.5f);
        o[j] = __float2bfloat16(fminf(fmaxf(qq, -1.f), 1.f));
    }
    *(uint2*)(dst + i) = *(uint2*)o;
}

// ---------------- fused norms + activation quant ----------------
template<int W, int WHICH>
__global__ void k_actquant(const float* __restrict__ X, const float* __restrict__ nw) {
    constexpr int VPT = W / 256;
    const int row = blockIdx.x, tid = threadIdx.x;
    const float* xr = (WHICH ? g_Y : X) + (size_t)row * W;
    float x[VPT];
    float ss = 0.f;
    #pragma unroll
    for (int i = 0; i < VPT; i++) { x[i] = xr[tid + i * 256]; ss += x[i] * x[i]; }
    ss = blockReduce<false>(ss);
    float r = rsqrtf(ss / (float)W + 1e-6f);
    float h[VPT]; float sum = 0.f, sq = 0.f;
    #pragma unroll
    for (int i = 0; i < VPT; i++) {
        h[i] = nw[tid + i * 256] * x[i] * r;
        sum += h[i]; sq += h[i] * h[i];
    }
    sum = blockReduce<false>(sum);
    sq  = blockReduce<false>(sq);
    float mean = sum / (float)W;
    float var  = sq / (float)W - mean * mean;
    float rv = rsqrtf(var + 1e-5f);
    float amax = 0.f;
    #pragma unroll
    for (int i = 0; i < VPT; i++) {
        h[i] = (h[i] - mean) * rv;
        amax = fmaxf(amax, fabsf(h[i]));
    }
    amax = blockReduce<true>(amax);
    float scale = 127.f / fmaxf(amax, 1e-5f);
    bf16* Q = WHICH ? g_Yq : g_Aq;
    #pragma unroll
    for (int i = 0; i < VPT; i++) {
        float q = rintf(h[i] * scale);
        q = fminf(fmaxf(q, -128.f), 127.f);
        Q[(size_t)row * W + tid + i * 256] = __float2bfloat16(q);
    }
    if (tid == 0) (WHICH ? g_sY : g_sA)[row] = scale;
}

// ---------------- pipelined mma.sync GEMM (R4 config: 128x128, 2 CTA/SM) ---
#define BMg 128
#define BNg 128
#define BKg 32
#define LDSg 40
#define STG_ELEMS (BMg * LDSg)
#define STG_BYTES (2 * STG_ELEMS * 2)
#define GEMM_SMEM (4 * STG_BYTES)

template<int MODE>
__global__ void __launch_bounds__(256, 2) k_gemm(const float* __restrict__ resid,
                                                 float* __restrict__ outp) {
    constexpr int K = MODE ? D_INNER_ : DIMX;
    constexpr int N = MODE ? DIMX : D_IN_PROJ_;
    constexpr int NS = K / BKg;

    const bf16*  __restrict__ A  = MODE ? g_Yq : g_Aq;
    const bf16*  __restrict__ Bw = MODE ? g_WqOut : g_WqIn;
    const float* __restrict__ rs = MODE ? g_sY : g_sA;
    float*       __restrict__ C  = MODE ? outp : g_ZX;

    extern __shared__ char smem[];
    const uint32_t sb = smem_u32(smem);

    const int tid = threadIdx.x;
    const int lane = tid & 31, wid = tid >> 5;
    const int wm = wid & 1, wn = wid >> 1;
    const int m0 = blockIdx.y * BMg, n0 = blockIdx.x * BNg;
    const int mw = wm * 64, nwp = wn * 32;

    float acc[4][4][4];
    #pragma unroll
    for (int a = 0; a < 4; a++)
        #pragma unroll
        for (int b = 0; b < 4; b++)
            #pragma unroll
            for (int c = 0; c < 4; c++) acc[a][b][c] = 0.f;

    const bf16* gsrc[4];
    uint32_t sdst[4];
    #pragma unroll
    for (int i = 0; i < 4; i++) {
        int q = tid + i * 256;
        if (q < 512) {
            int row = q >> 2, c = q & 3;
            gsrc[i] = A + (size_t)(m0 + row) * K + c * 8;
            sdst[i] = (uint32_t)(row * LDSg + c * 8) * 2;
        } else {
            int qq = q - 512, row = qq >> 2, c = qq & 3;
            gsrc[i] = Bw + (size_t)(n0 + row) * K + c * 8;
            sdst[i] = (uint32_t)(STG_ELEMS + row * LDSg + c * 8) * 2;
        }
    }

    #define LOAD_STAGE(s_) do { \
        uint32_t base_ = sb + ((s_) & 3) * STG_BYTES; \
        _Pragma("unroll") \
        for (int i_ = 0; i_ < 4; i_++) \
            asm volatile("cp.async.cg.shared.global [%0], [%1], 16;" \
                :: "r"(base_ + sdst[i_]), "l"(gsrc[i_] + (s_) * BKg) : "memory"); \
        asm volatile("cp.async.commit_group;" ::: "memory"); \
    } while (0)

    uint32_t aOff[4], bOff[2];
    {
        int rA = mw + (lane & 15);
        int cA = (lane >> 4) * 8;
        #pragma unroll
        for (int fm = 0; fm < 4; fm++)
            aOff[fm] = (uint32_t)((rA + fm * 16) * LDSg + cA) * 2;
        int rB = nwp + ((lane >> 4) << 3) + (lane & 7);
        int cB = ((lane >> 3) & 1) * 8;
        #pragma unroll
        for (int fb = 0; fb < 2; fb++)
            bOff[fb] = (uint32_t)(STG_ELEMS + (rB + fb * 16) * LDSg + cB) * 2;
    }

    LOAD_STAGE(0); LOAD_STAGE(1); LOAD_STAGE(2);

    for (int s = 0; s < NS; s++) {
        asm volatile("cp.async.wait_group 2;" ::: "memory");
        __syncthreads();
        if (s + 3 < NS) LOAD_STAGE(s + 3);

        const uint32_t base = sb + (s & 3) * STG_BYTES;
        #pragma unroll
        for (int ks = 0; ks < BKg; ks += 16) {
            unsigned af[4][4], bfr[4][2];
            #pragma unroll
            for (int fm = 0; fm < 4; fm++)
                asm volatile("ldmatrix.sync.aligned.m8n8.x4.shared.b16 {%0,%1,%2,%3}, [%4];"
                    : "=r"(af[fm][0]), "=r"(af[fm][1]), "=r"(af[fm][2]), "=r"(af[fm][3])
                    : "r"(base + aOff[fm] + (uint32_t)(ks * 2)));
            #pragma unroll
            for (int fb = 0; fb < 2; fb++) {
                unsigned q0, q1, q2, q3;
                asm volatile("ldmatrix.sync.aligned.m8n8.x4.shared.b16 {%0,%1,%2,%3}, [%4];"
                    : "=r"(q0), "=r"(q1), "=r"(q2), "=r"(q3)
                    : "r"(base + bOff[fb] + (uint32_t)(ks * 2)));
                bfr[fb * 2][0] = q0; bfr[fb * 2][1] = q1;
                bfr[fb * 2 + 1][0] = q2; bfr[fb * 2 + 1][1] = q3;
            }
            #pragma unroll
            for (int fm = 0; fm < 4; fm++)
                #pragma unroll
                for (int fn = 0; fn < 4; fn++)
                    asm volatile("mma.sync.aligned.m16n8k16.row.col.f32.bf16.bf16.f32 "
                        "{%0,%1,%2,%3},{%4,%5,%6,%7},{%8,%9},{%0,%1,%2,%3};"
                        : "+f"(acc[fm][fn][0]), "+f"(acc[fm][fn][1]),
                          "+f"(acc[fm][fn][2]), "+f"(acc[fm][fn][3])
                        : "r"(af[fm][0]), "r"(af[fm][1]), "r"(af[fm][2]), "r"(af[fm][3]),
                          "r"(bfr[fn][0]), "r"(bfr[fn][1]));
        }
    }

    const int mr = m0 + mw + (lane >> 2);
    const int nc = n0 + nwp + (lane & 3) * 2;
    #pragma unroll
    for (int fm = 0; fm < 4; fm++) {
        int m = mr + fm * 16;
        float inv0 = 1.f / rs[m];
        float inv1 = 1.f / rs[m + 8];
        #pragma unroll
        for (int fn = 0; fn < 4; fn++) {
            int n = nc + fn * 8;
            if (n < N) {
                size_t o0 = (size_t)m * N + n;
                size_t o8 = (size_t)(m + 8) * N + n;
                float v0 = acc[fm][fn][0] * inv0;
                float v1 = acc[fm][fn][1] * inv0;
                float v2 = acc[fm][fn][2] * inv1;
                float v3 = acc[fm][fn][3] * inv1;
                if (MODE) {
                    v0 += resid[o0]; v1 += resid[o0 + 1];
                    v2 += resid[o8]; v3 += resid[o8 + 1];
                }
                C[o0] = v0; C[o0 + 1] = v1; C[o8] = v2; C[o8 + 1] = v3;
            }
        }
    }
    #undef LOAD_STAGE
}

// ---------------- causal conv1d + silu: sliding window ----------------
__global__ void k_conv(const float* __restrict__ cw, const float* __restrict__ cb) {
    int c = blockIdx.x * 256 + threadIdx.x;
    if (c >= CONV_DIM_) return;
    int b = blockIdx.y >> 3;
    int s0 = (blockIdx.y & 7) * 256;
    const float* src = g_ZX + (size_t)(b * SEQ_) * D_IN_PROJ_ + D_INNER_ + c;
    float*       dst = g_XC + (size_t)(b * SEQ_) * CONV_DIM_ + c;
    const float w0 = cw[c * 4], w1 = cw[c * 4 + 1], w2 = cw[c * 4 + 2], w3 = cw[c * 4 + 3];
    const float bias = cb[c];
    float xm3 = 0.f, xm2 = 0.f, xm1 = 0.f;
    if (s0 > 0) {
        xm3 = src[(size_t)(s0 - 3) * D_IN_PROJ_];
        xm2 = src[(size_t)(s0 - 2) * D_IN_PROJ_];
        xm1 = src[(size_t)(s0 - 1) * D_IN_PROJ_];
    }
    #pragma unroll 4
    for (int l = s0; l < s0 + 256; l++) {
        float x0 = src[(size_t)l * D_IN_PROJ_];
        float acc = fmaf(w3, x0, fmaf(w2, xm1, fmaf(w1, xm2, fmaf(w0, xm3, bias))));
        dst[(size_t)l * CONV_DIM_] = acc / (1.f + expf(-acc));
        xm3 = xm2; xm2 = xm1; xm1 = x0;
    }
}

// ---------------- recurrent SSD scan: 2 steps/barrier, LDS.128 B/C --------
__global__ void __launch_bounds__(512) k_scan(const float* __restrict__ A_log,
                                              const float* __restrict__ Dv,
                                              const float* __restrict__ dt_bias) {
    const int bh = blockIdx.x;
    const int h = bh & (NHEADS_ - 1);
    const int b = bh >> 6;
    const int t = threadIdx.x;
    const int pc = t & 63, gc = t >> 6, n0 = gc * 16;

    __shared__ __align__(16) float xs[2][2][64], zs[2][2][64];
    __shared__ __align__(16) float Bsh[2][2][128], Csh[2][2][128];
    __shared__ __align__(16) float ypart[2][2][8][64];
    __shared__ float sdt[2][2], sdA[2][2];

    const float Ah   = -expf(A_log[h]);
    const float Dh   = Dv[h];
    const float bias = dt_bias[h];

    u64 h2[8];
    #pragma unroll
    for (int i = 0; i < 8; i++) h2[i] = 0ull;

    const float* gptr = nullptr;
    if      (t < 64)  gptr = g_XC + (size_t)(b * SEQ_) * CONV_DIM_ + h * 64 + t;
    else if (t < 192) gptr = g_XC + (size_t)(b * SEQ_) * CONV_DIM_ + D_INNER_ + (t - 64);
    else if (t < 320) gptr = g_XC + (size_t)(b * SEQ_) * CONV_DIM_ + D_INNER_ + D_STATE_ + (t - 192);
    else if (t < 384) gptr = g_ZX + (size_t)(b * SEQ_) * D_IN_PROJ_ + h * 64 + (t - 320);
    else if (t == 384) gptr = g_ZX + (size_t)(b * SEQ_) * D_IN_PROJ_ + DT_OFF_ + h;
    const size_t stride = (t < 320) ? (size_t)CONV_DIM_ : (size_t)D_IN_PROJ_;

    float v0 = 0.f, v1 = 0.f;
    if (gptr) { v0 = gptr[0]; v1 = gptr[stride]; }
    float* yrow = g_Y + (size_t)(b * SEQ_) * D_INNER_ + h * 64;

    for (int blk = 0; blk < SEQ_ / 2; blk++) {
        const int p = blk & 1, q = p ^ 1;
        if      (t < 64)  { xs[p][0][t] = v0;        xs[p][1][t] = v1; }
        else if (t < 192) { Bsh[p][0][t - 64] = v0;  Bsh[p][1][t - 64] = v1; }
        else if (t < 320) { Csh[p][0][t - 192] = v0; Csh[p][1][t - 192] = v1; }
        else if (t < 384) { zs[p][0][t - 320] = v0;  zs[p][1][t - 320] = v1; }
        else if (t == 384) {
            float d0 = v0 + bias;
            float sp0 = fmaxf(d0, 0.f) + log1pf(expf(-fabsf(d0)));
            sdt[p][0] = sp0; sdA[p][0] = expf(sp0 * Ah);
            float d1 = v1 + bias;
            float sp1 = fmaxf(d1, 0.f) + log1pf(expf(-fabsf(d1)));
            sdt[p][1] = sp1; sdA[p][1] = expf(sp1 * Ah);
        }
        __syncthreads();

        if (blk > 0 && t < 64) {
            #pragma unroll
            for (int s = 0; s < 2; s++) {
                float ysum = 0.f;
                #pragma unroll
                for (int g = 0; g < 8; g++) ysum += ypart[q][s][g][t];
                float xv = xs[q][s][t], zz = zs[q][s][t];
                float yo = (ysum + Dh * xv) * (zz / (1.f + expf(-zz)));
                yrow[(size_t)(2 * (blk - 1) + s) * D_INNER_ + t] = yo;
            }
        }

        float v0n = 0.f, v1n = 0.f;
        if (gptr && blk + 1 < SEQ_ / 2) {
            v0n = gptr[(size_t)(2 * blk + 2) * stride];
            v1n = gptr[(size_t)(2 * blk + 3) * stride];
        }

        #pragma unroll
        for (int s = 0; s < 2; s++) {
            const float dA = sdA[p][s];
            const float cf = sdt[p][s] * xs[p][s][pc];
            const u64 dA2 = pk2(dA, dA);
            const u64 cf2 = pk2(cf, cf);
            const ulonglong2* Bv = (const ulonglong2*)&Bsh[p][s][n0];
            const ulonglong2* Cv = (const ulonglong2*)&Csh[p][s][n0];
            u64 y2 = 0ull;
            #pragma unroll
            for (int i = 0; i < 4; i++) {
                ulonglong2 B2 = Bv[i];
                ulonglong2 C2 = Cv[i];
                h2[2 * i]     = fma2(h2[2 * i],     dA2, mul2(cf2, B2.x));
                y2 = fma2(h2[2 * i],     C2.x, y2);
                h2[2 * i + 1] = fma2(h2[2 * i + 1], dA2, mul2(cf2, B2.y));
                y2 = fma2(h2[2 * i + 1], C2.y, y2);
            }
            float ylo, yhi; upk2(ylo, yhi, y2);
            ypart[p][s][gc][pc] = ylo + yhi;
        }

        v0 = v0n; v1 = v1n;
    }
    __syncthreads();
    if (t < 64) {
        const int q = (SEQ_ / 2 - 1) & 1;
        #pragma unroll
        for (int s = 0; s < 2; s++) {
            float ysum = 0.f;
            #pragma unroll
            for (int g = 0; g < 8; g++) ysum += ypart[q][s][g][t];
            float xv = xs[q][s][t], zz = zs[q][s][t];
            float yo = (ysum + Dh * xv) * (zz / (1.f + expf(-zz)));
            yrow[(size_t)(SEQ_ - 2 + s) * D_INNER_ + t] = yo;
        }
    }
}

// ---------------- launch ----------------
extern "C" void kernel_launch(void* const* d_in, const int* in_sizes, int n_in,
                              void* d_out, int out_size) {
    const float* hidden     = (const float*)d_in[0];
    const float* in_proj    = (const float*)d_in[1];
    const float* out_proj   = (const float*)d_in[2];
    const float* conv_w     = (const float*)d_in[3];
    const float* conv_b     = (const float*)d_in[4];
    const float* A_log      = (const float*)d_in[5];
    const float* Dv         = (const float*)d_in[6];
    const float* dt_bias    = (const float*)d_in[7];
    const float* norm_w     = (const float*)d_in[8];
    const float* out_norm_w = (const float*)d_in[9];
    float* out = (float*)d_out;

    const long nW1 = (long)D_IN_PROJ_ * DIMX;
    const long nW2 = (long)DIMX * D_INNER_;
    const long nQAll = NQ1 + NQ2 + NQP;

    cudaFuncSetAttribute(k_gemm<0>, cudaFuncAttributeMaxDynamicSharedMemorySize, GEMM_SMEM);
    cudaFuncSetAttribute(k_gemm<1>, cudaFuncAttributeMaxDynamicSharedMemorySize, GEMM_SMEM);

    k_absboth<<<2048, 256>>>((const float4*)in_proj, (const float4*)out_proj, nW1 / 4, nW2 / 4);
    k_wscale_final<<<1, 256>>>();
    k_wquant_all<<<(unsigned)((nQAll + 255) / 256), 256>>>(in_proj, out_proj);
    k_actquant<DIMX, 0><<<MROWS_, 256>>>(hidden, norm_w);
    k_gemm<0><<<dim3((D_IN_PROJ_ + 127) / 128, MROWS_ / 128), 256, GEMM_SMEM>>>(nullptr, nullptr);
    k_conv<<<dim3((CONV_DIM_ + 255) / 256, BATCH_ * 8), 256>>>(conv_w, conv_b);
    k_scan<<<BATCH_ * NHEADS_, 512>>>(A_log, Dv, dt_bias);
    k_actquant<D_INNER_, 1><<<MROWS_, 256>>>(nullptr, out_norm_w);
    k_gemm<1><<<dim3(DIMX / 128, MROWS_ / 128), 256, GEMM_SMEM>>>(hidden, out);
}